// round 2
// baseline (speedup 1.0000x reference)
#include <cuda_runtime.h>
#include <math.h>

// Problem dims
#define BB   64      // batch
#define TT   512     // seq len
#define EE   256     // embed
#define HH   512     // hidden
#define GG   2048    // 4*HH
#define KC   64      // k-chunk
#define WSTR 36      // weight tile row stride (32 cols + pad, 16B-aligned rows)

// ---------------- device scratch (allocation-free) ----------------
__device__ float g_X[TT * EE * BB];        // [t][e][b]  33.5 MB
__device__ float g_h1[2][2][HH * BB];      // [dir][parity][k][b]
__device__ float g_h2[2][2][HH * BB];
__device__ unsigned g_bar[2];
__device__ int g_tok32;                    // 1 if tokens are int32

// ---------------- helpers ----------------
__device__ __forceinline__ float sigf(float x) { return 1.0f / (1.0f + expf(-x)); }

__device__ __forceinline__ void grid_bar(unsigned* ctr, unsigned target) {
    __syncthreads();
    if (threadIdx.x == 0) {
        __threadfence();                 // release our h writes to GPU scope
        atomicAdd(ctr, 1u);
        while (*((volatile unsigned*)ctr) < target) { }
    }
    __syncthreads();
}

// ---------------- reset ----------------
__global__ void reset_kernel() {
    int i = blockIdx.x * blockDim.x + threadIdx.x;
    if (i < HH * BB) {
        #pragma unroll
        for (int d = 0; d < 2; d++)
            #pragma unroll
            for (int p = 0; p < 2; p++) { g_h1[d][p][i] = 0.0f; g_h2[d][p][i] = 0.0f; }
    }
    if (i == 0) { g_bar[0] = 0u; g_bar[1] = 0u; }
}

// ---------------- token dtype detect ----------------
// If tokens are int64 little-endian with values < 50000, every odd 32-bit word is 0.
// Only scan the first 32768 words (safe under both interpretations).
__global__ void detect_kernel(const unsigned* tok) {
    __shared__ unsigned red[256];
    unsigned v = 0;
    for (int i = threadIdx.x; i < 16384; i += 256) v |= tok[2 * i + 1];
    red[threadIdx.x] = v;
    __syncthreads();
    for (int s = 128; s > 0; s >>= 1) {
        if (threadIdx.x < s) red[threadIdx.x] |= red[threadIdx.x + s];
        __syncthreads();
    }
    if (threadIdx.x == 0) g_tok32 = (red[0] != 0u) ? 1 : 0;
}

// ---------------- embedding gather (X[t][e][b]) ----------------
__global__ void gather_kernel(const void* tokens, const float* emb) {
    int t = blockIdx.x;        // 0..511
    int b = blockIdx.y;        // 0..63
    int e = threadIdx.x;       // 0..255
    long idx;
    if (g_tok32) idx = (long)((const int*)tokens)[b * TT + t];
    else         idx = (long)((const unsigned*)tokens)[(size_t)(b * TT + t) * 2];
    g_X[((size_t)t * EE + e) * BB + b] = emb[idx * EE + e];
}

// ---------------- GEMM chunk helper ----------------
// acc[j] += sum_k src[k][b] * Wg[k][cg*512 + ub + j]  over nk rows (nk % 64 == 0)
__device__ __forceinline__ void gemm_chunks(
    float acc[8], const float* __restrict__ src, int nk,
    const float* __restrict__ Wg, int ub,
    int tid, int b, int cg, float* wt, float* ht)
{
    const int skl = tid & 63;       // k-local row this thread stages
    const int sseg = tid >> 6;      // gate segment this thread stages
    for (int k0 = 0; k0 < nk; k0 += KC) {
        // prefetch into registers (overlaps previous chunk's compute)
        const float4* wsrc = (const float4*)(Wg + (size_t)(k0 + skl) * GG + sseg * HH + ub);
        float4 wv0 = wsrc[0];
        float4 wv1 = wsrc[1];
        const float4* hsrc = (const float4*)(src + (size_t)k0 * BB);
        float4 h0 = __ldcg(hsrc + tid);
        float4 h1 = __ldcg(hsrc + tid + 256);
        float4 h2 = __ldcg(hsrc + tid + 512);
        float4 h3 = __ldcg(hsrc + tid + 768);
        __syncthreads();   // previous chunk's compute done before overwrite
        ((float4*)(wt + skl * WSTR + sseg * 8))[0] = wv0;
        ((float4*)(wt + skl * WSTR + sseg * 8))[1] = wv1;
        ((float4*)ht)[tid      ] = h0;
        ((float4*)ht)[tid + 256] = h1;
        ((float4*)ht)[tid + 512] = h2;
        ((float4*)ht)[tid + 768] = h3;
        __syncthreads();
        #pragma unroll 16
        for (int k = 0; k < KC; k++) {
            float hv = ht[k * BB + b];
            const float4* wrow = (const float4*)(wt + k * WSTR + cg * 8);
            float4 u0 = wrow[0];
            float4 u1 = wrow[1];
            acc[0] += hv * u0.x; acc[1] += hv * u0.y;
            acc[2] += hv * u0.z; acc[3] += hv * u0.w;
            acc[4] += hv * u1.x; acc[5] += hv * u1.y;
            acc[6] += hv * u1.z; acc[7] += hv * u1.w;
        }
    }
}

// ---------------- persistent BiLSTM kernel ----------------
__global__ void __launch_bounds__(256, 1) lstm_kernel(
    const float* __restrict__ W1f, const float* __restrict__ U1f, const float* __restrict__ b1f,
    const float* __restrict__ W2f, const float* __restrict__ U2f, const float* __restrict__ b2f,
    const float* __restrict__ W1b, const float* __restrict__ U1b, const float* __restrict__ b1b,
    const float* __restrict__ W2b, const float* __restrict__ U2b, const float* __restrict__ b2b)
{
    const int dir = blockIdx.x >> 6;     // 0 = fwd, 1 = bwd
    const int cid = blockIdx.x & 63;     // CTA within direction
    const int ub  = cid * 8;             // base hidden unit
    const int tid = threadIdx.x;
    const int b   = tid & 63;
    const int cg  = tid >> 6;            // gate: 0=i 1=f 2=g 3=o

    const float *W1, *U1, *b1, *W2, *U2, *b2;
    if (dir == 0) { W1 = W1f; U1 = U1f; b1 = b1f; W2 = W2f; U2 = U2f; b2 = b2f; }
    else          { W1 = W1b; U1 = U1b; b1 = b1b; W2 = W2b; U2 = U2b; b2 = b2b; }

    __shared__ float wt[KC * WSTR];      // 9216 B
    __shared__ float ht[KC * BB];        // 16384 B
    __shared__ float zb[GG];             // 8192 B (32 cols x 64 b as [gate*8+u][b])

    // cell state lives in registers: this thread owns pairs p=tid and p=tid+256,
    // where p = u*64 + b' (u in 0..7 local unit, b' batch)
    float c1_0 = 0.0f, c1_1 = 0.0f, c2_0 = 0.0f, c2_1 = 0.0f;
    unsigned target = 0;
    float* h1w[2] = { g_h1[dir][0], g_h1[dir][1] };
    float* h2w[2] = { g_h2[dir][0], g_h2[dir][1] };

    for (int t = 0; t < TT; t++) {
        const int ttx = dir ? (TT - 1 - t) : t;
        const int wp = t & 1, rp = wp ^ 1;

        // ================= Phase A: layer-1 gates =================
        float acc[8];
        #pragma unroll
        for (int j = 0; j < 8; j++) acc[j] = b1[cg * HH + ub + j];
        gemm_chunks(acc, g_X + (size_t)ttx * EE * BB, EE, W1, ub, tid, b, cg, wt, ht);
        gemm_chunks(acc, h1w[rp], HH, U1, ub, tid, b, cg, wt, ht);

        __syncthreads();
        #pragma unroll
        for (int j = 0; j < 8; j++) zb[(cg * 8 + j) * BB + b] = acc[j];
        __syncthreads();
        {
            // pair 0
            int u = tid >> 6, bb2 = tid & 63;
            float iv = zb[( 0 + u) * BB + bb2];
            float fv = zb[( 8 + u) * BB + bb2];
            float gv = zb[(16 + u) * BB + bb2];
            float ov = zb[(24 + u) * BB + bb2];
            float c = sigf(fv) * c1_0 + sigf(iv) * tanhf(gv);
            c1_0 = c;
            __stcg(&h1w[wp][(ub + u) * BB + bb2], sigf(ov) * tanhf(c));
            // pair 1
            u += 4;
            iv = zb[( 0 + u) * BB + bb2];
            fv = zb[( 8 + u) * BB + bb2];
            gv = zb[(16 + u) * BB + bb2];
            ov = zb[(24 + u) * BB + bb2];
            c = sigf(fv) * c1_1 + sigf(iv) * tanhf(gv);
            c1_1 = c;
            __stcg(&h1w[wp][(ub + u) * BB + bb2], sigf(ov) * tanhf(c));
        }
        target += 64;
        grid_bar(&g_bar[dir], target);

        // ================= Phase B: layer-2 gates =================
        #pragma unroll
        for (int j = 0; j < 8; j++) acc[j] = b2[cg * HH + ub + j];
        gemm_chunks(acc, h1w[wp], HH, W2, ub, tid, b, cg, wt, ht);
        gemm_chunks(acc, h2w[rp], HH, U2, ub, tid, b, cg, wt, ht);

        __syncthreads();
        #pragma unroll
        for (int j = 0; j < 8; j++) zb[(cg * 8 + j) * BB + b] = acc[j];
        __syncthreads();
        {
            int u = tid >> 6, bb2 = tid & 63;
            float iv = zb[( 0 + u) * BB + bb2];
            float fv = zb[( 8 + u) * BB + bb2];
            float gv = zb[(16 + u) * BB + bb2];
            float ov = zb[(24 + u) * BB + bb2];
            float c = sigf(fv) * c2_0 + sigf(iv) * tanhf(gv);
            c2_0 = c;
            __stcg(&h2w[wp][(ub + u) * BB + bb2], sigf(ov) * tanhf(c));
            u += 4;
            iv = zb[( 0 + u) * BB + bb2];
            fv = zb[( 8 + u) * BB + bb2];
            gv = zb[(16 + u) * BB + bb2];
            ov = zb[(24 + u) * BB + bb2];
            c = sigf(fv) * c2_1 + sigf(iv) * tanhf(gv);
            c2_1 = c;
            __stcg(&h2w[wp][(ub + u) * BB + bb2], sigf(ov) * tanhf(c));
        }
        target += 64;
        grid_bar(&g_bar[dir], target);
    }
}

// ---------------- final dense head ----------------
__global__ void dense_kernel(const float* __restrict__ Wd, const float* __restrict__ bd,
                             float* __restrict__ out) {
    int tid = threadIdx.x;
    if (tid >= 320) return;
    int bb2 = tid / 5, o = tid % 5;
    // last step t=511 wrote parity 1
    float s = bd[o];
    for (int j = 0; j < HH; j++) s += g_h2[0][1][j * BB + bb2] * Wd[j * 5 + o];
    for (int j = 0; j < HH; j++) s += g_h2[1][1][j * BB + bb2] * Wd[(HH + j) * 5 + o];
    out[bb2 * 5 + o] = s;
}

// ---------------- launch ----------------
extern "C" void kernel_launch(void* const* d_in, const int* in_sizes, int n_in,
                              void* d_out, int out_size) {
    const void*  tokens = d_in[0];
    const float* emb = (const float*)d_in[1];
    const float* W1f = (const float*)d_in[2];
    const float* U1f = (const float*)d_in[3];
    const float* b1f = (const float*)d_in[4];
    const float* W2f = (const float*)d_in[5];
    const float* U2f = (const float*)d_in[6];
    const float* b2f = (const float*)d_in[7];
    const float* W1b = (const float*)d_in[8];
    const float* U1b = (const float*)d_in[9];
    const float* b1b = (const float*)d_in[10];
    const float* W2b = (const float*)d_in[11];
    const float* U2b = (const float*)d_in[12];
    const float* b2b = (const float*)d_in[13];
    const float* Wd  = (const float*)d_in[14];
    const float* bd  = (const float*)d_in[15];
    float* out = (float*)d_out;

    reset_kernel<<<128, 256>>>();
    detect_kernel<<<1, 256>>>((const unsigned*)tokens);
    dim3 gg(TT, BB);
    gather_kernel<<<gg, 256>>>(tokens, emb);
    lstm_kernel<<<128, 256>>>(W1f, U1f, b1f, W2f, U2f, b2f,
                              W1b, U1b, b1b, W2b, U2b, b2b);
    dense_kernel<<<1, 320>>>(Wd, bd, out);
}